// round 9
// baseline (speedup 1.0000x reference)
#include <cuda_runtime.h>
#include <cuda_fp16.h>
#include <cstdint>
#include <cstddef>

// ---------------- problem constants ----------------
#define C_INC   128
#define C_OUTC  256
#define HDIM    64
#define WDIM    64
#define BSZ     16
#define KKC     1152          // C_IN * 9
#define M_TOT   65536
#define L_IMG   4096

// ---------------- k_aq staging ----------------
#define STRH    1156
#define AQ_SMEM (576*4 + 8*3*66*4 + 64*STRH)   // 82624

// ---------------- GEMM tiling ----------------
#define BM   128
#define BN   256
#define KT_STEPS 18           // chunks of 64 halves (128 B)
#define SROW 144              // smem row stride bytes
#define A_STG (BM * SROW)     // 18432
#define B_STG (BN * SROW)     // 36864
#define STG_BOTH (A_STG + B_STG)
#define NSTAGE 3
#define GEMM_SMEM (NSTAGE * STG_BOTH)   // 165888

// ---------------- device scratch ----------------
__device__ float g_wscale[KKC];
__device__ float g_ascale[KKC];
__device__ float g_scale[KKC];
__device__ float g_qfx[KKC];
__device__ float g_sx;
__device__ float g_sw;
__device__ __align__(16) __half g_wq_h[C_OUTC * KKC];
__device__ __align__(16) __half g_aq_h[(size_t)M_TOT * KKC];   // 151 MB

// ---------------- K1: weight per-column max (+ reset ascale) ----------------
__global__ void k_wscale(const float* __restrict__ w) {
    int j = blockIdx.x * blockDim.x + threadIdx.x;
    if (j >= KKC) return;
    g_ascale[j] = 0.f;
    float m = 0.f;
    for (int o = 0; o < C_OUTC; ++o)
        m = fmaxf(m, fabsf(w[o * KKC + j]));
    g_wscale[j] = m;
}

// ---------------- K2: activation per-(c,kh,kw) max -------------------------
__global__ void k_ascale(const float* __restrict__ x) {
    int c = blockIdx.x, b = blockIdx.y;
    float m[9];
#pragma unroll
    for (int v = 0; v < 9; ++v) m[v] = 0.f;

    const float* xb = x + (((size_t)b * C_INC + c) << 12);
    for (int p = threadIdx.x; p < L_IMG; p += 256) {
        int h = p >> 6, w = p & 63;
        float a = fabsf(xb[p]);
        bool h0 = (h < HDIM - 1);
        bool h2 = (h > 0);
        bool w0 = (w < WDIM - 1);
        bool w2 = (w > 0);
        if (h0 && w0) m[0] = fmaxf(m[0], a);
        if (h0)       m[1] = fmaxf(m[1], a);
        if (h0 && w2) m[2] = fmaxf(m[2], a);
        if (w0)       m[3] = fmaxf(m[3], a);
        m[4] = fmaxf(m[4], a);
        if (w2)       m[5] = fmaxf(m[5], a);
        if (h2 && w0) m[6] = fmaxf(m[6], a);
        if (h2)       m[7] = fmaxf(m[7], a);
        if (h2 && w2) m[8] = fmaxf(m[8], a);
    }

    __shared__ float sm[256];
    for (int v = 0; v < 9; ++v) {
        sm[threadIdx.x] = m[v];
        __syncthreads();
        for (int s = 128; s > 0; s >>= 1) {
            if (threadIdx.x < s)
                sm[threadIdx.x] = fmaxf(sm[threadIdx.x], sm[threadIdx.x + s]);
            __syncthreads();
        }
        if (threadIdx.x == 0)
            atomicMax((int*)&g_ascale[c * 9 + v], __float_as_int(sm[0]));
        __syncthreads();
    }
}

// ---------------- K3: smooth scales + per-tensor quant scales ---------------
__global__ void k_scale() {
    __shared__ float red[256];
    __shared__ float s_sx_sh;
    int tid = threadIdx.x;

    float mx = 0.f, mw = 0.f;
    for (int j = tid; j < KKC; j += 256) {
        float a = g_ascale[j];
        float w = g_wscale[j];
        float s = __fdiv_rn(__fsqrt_rn(a), __fsqrt_rn(w));
        if (s == 0.f) s = 1.f;
        g_scale[j] = s;
        mx = fmaxf(mx, __fdiv_rn(a, s));
        mw = fmaxf(mw, w * s);
    }

    red[tid] = mx; __syncthreads();
    for (int s = 128; s > 0; s >>= 1) {
        if (tid < s) red[tid] = fmaxf(red[tid], red[tid + s]);
        __syncthreads();
    }
    if (tid == 0) {
        float sx = __fdiv_rn(red[0], 127.f);
        if (sx == 0.f) sx = 1.f;
        g_sx = sx; s_sx_sh = sx;
    }
    __syncthreads();

    red[tid] = mw; __syncthreads();
    for (int s = 128; s > 0; s >>= 1) {
        if (tid < s) red[tid] = fmaxf(red[tid], red[tid + s]);
        __syncthreads();
    }
    if (tid == 0) {
        float sw = __fdiv_rn(red[0], 127.f);
        if (sw == 0.f) sw = 1.f;
        g_sw = sw;
    }
    __syncthreads();

    float sx = s_sx_sh;
    for (int j = tid; j < KKC; j += 256)
        g_qfx[j] = __fdiv_rn(1.f, g_scale[j] * sx);
}

// ---------------- K4: quantize weights -> fp16 ------------------------------
__global__ void k_wq(const float* __restrict__ w) {
    int i = blockIdx.x * blockDim.x + threadIdx.x;
    if (i >= C_OUTC * KKC) return;
    int j = i % KKC;
    float t = w[i] * g_scale[j];
    float q = rintf(__fdiv_rn(t, g_sw));
    q = fminf(fmaxf(q, -127.f), 127.f);
    g_wq_h[i] = __float2half_rn(q);
}

// ---------------- K5: fused im2col + quantization -> fp16 -------------------
__global__ void __launch_bounds__(256) k_aq(const float* __restrict__ x) {
    extern __shared__ char dsm[];
    float*  qfx_s = (float*)dsm;
    float*  xs    = qfx_s + 576;
    __half* aqs   = (__half*)(xs + 8 * 3 * 66);

    int tid = threadIdx.x;
    int bh  = blockIdx.x;
    int ch2 = blockIdx.y;
    int b   = bh >> 6, h = bh & 63;
    int g   = tid >> 5, lane = tid & 31;

    for (int j = tid; j < 576; j += 256) qfx_s[j] = g_qfx[ch2 * 576 + j];

    float* xg = xs + g * (3 * 66);

    for (int c0 = 0; c0 < 64; c0 += 8) {
        int cl = c0 + g;
        int c  = ch2 * 64 + cl;
        __syncthreads();
        const float* xb = x + (((size_t)b * C_INC + c) << 12);
#pragma unroll
        for (int r = 0; r < 3; ++r) {
            int hh = h + r - 1;
            float v0 = 0.f, v1 = 0.f;
            if ((unsigned)hh < (unsigned)HDIM) {
                v0 = xb[(hh << 6) + lane];
                v1 = xb[(hh << 6) + lane + 32];
            }
            xg[r * 66 + 1 + lane]  = v0;
            xg[r * 66 + 33 + lane] = v1;
            if (lane == 0) { xg[r * 66] = 0.f; xg[r * 66 + 65] = 0.f; }
        }
        __syncthreads();
#pragma unroll
        for (int half = 0; half < 2; ++half) {
            int w = lane + half * 32;
            __half* ar = (__half*)((char*)aqs + w * STRH);
#pragma unroll
            for (int e = 0; e < 9; ++e) {
                const int kh = e / 3, kw = e % 3;
                float v = xg[kh * 66 + w + kw];
                float q = rintf(v * qfx_s[cl * 9 + e]);
                q = fminf(fmaxf(q, -127.f), 127.f);
                ar[cl * 9 + e] = __float2half_rn(q);
            }
        }
    }
    __syncthreads();

    int* dst = (int*)g_aq_h;
    for (int idx = tid; idx < 64 * 288; idx += 256) {
        int row = idx / 288;
        int col = idx - row * 288;
        dst[((size_t)(bh * 64 + row)) * 576 + ch2 * 288 + col] =
            *(const int*)((char*)aqs + row * STRH + col * 4);
    }
}

// ---------------- K6: fp16 HMMA GEMM, BN=256 (A read once) ------------------
__device__ __forceinline__ void cp16(void* smem_dst, const void* gmem_src) {
    unsigned s = (unsigned)__cvta_generic_to_shared(smem_dst);
    asm volatile("cp.async.cg.shared.global [%0], [%1], 16;\n"
                 :: "r"(s), "l"(gmem_src));
}

__device__ __forceinline__ void ldsm4(uint32_t* r, const void* p) {
    unsigned a = (unsigned)__cvta_generic_to_shared(p);
    asm volatile("ldmatrix.sync.aligned.m8n8.x4.shared.b16 {%0,%1,%2,%3}, [%4];"
                 : "=r"(r[0]), "=r"(r[1]), "=r"(r[2]), "=r"(r[3]) : "r"(a));
}

__device__ __forceinline__ void mma_f16(float* c, const uint32_t* a,
                                        uint32_t b0, uint32_t b1) {
    asm volatile(
        "mma.sync.aligned.m16n8k16.row.col.f32.f16.f16.f32 "
        "{%0,%1,%2,%3}, {%4,%5,%6,%7}, {%8,%9}, {%0,%1,%2,%3};\n"
        : "+f"(c[0]), "+f"(c[1]), "+f"(c[2]), "+f"(c[3])
        : "r"(a[0]), "r"(a[1]), "r"(a[2]), "r"(a[3]), "r"(b0), "r"(b1));
}

__global__ void __launch_bounds__(512, 1) k_gemm_h(const float* __restrict__ bias,
                                                   float* __restrict__ out) {
    extern __shared__ __align__(16) char smem[];

    int tid = threadIdx.x;
    int warpId = tid >> 5, lane = tid & 31;
    int wm = warpId & 3, wn = warpId >> 2;   // 4(m) x 4(n); warp tile 32x64
    size_t m0 = (size_t)blockIdx.x * BM;

    float acc[2][8][4];
#pragma unroll
    for (int i = 0; i < 2; ++i)
#pragma unroll
        for (int j = 0; j < 8; ++j)
#pragma unroll
            for (int r = 0; r < 4; ++r) acc[i][j][r] = 0.f;

    const char* Ag = (const char*)g_aq_h;    // row stride 2304 B
    const char* Bg = (const char*)g_wq_h;

    auto load_stage = [&](int kt, int s) {
        char* As = smem + s * STG_BOTH;
        char* Bs = As + A_STG;
#pragma unroll
        for (int it = 0; it < 2; ++it) {     // A: 1024 granules
            int f = tid + it * 512;
            int row = f >> 3, c16 = f & 7;
            cp16(As + row * SROW + c16 * 16,
                 Ag + (m0 + row) * 2304 + kt * 128 + c16 * 16);
        }
#pragma unroll
        for (int it = 0; it < 4; ++it) {     // B: 2048 granules
            int f = tid + it * 512;
            int row = f >> 3, c16 = f & 7;
            cp16(Bs + row * SROW + c16 * 16,
                 Bg + (size_t)row * 2304 + kt * 128 + c16 * 16);
        }
        asm volatile("cp.async.commit_group;\n" ::: "memory");
    };

    load_stage(0, 0);
    load_stage(1, 1);

    int lrow = lane & 15;
    int lcol = (lane >> 4) * 16;

    for (int kt = 0; kt < KT_STEPS; ++kt) {
        if (kt + 2 < KT_STEPS) {
            load_stage(kt + 2, (kt + 2) % NSTAGE);
            asm volatile("cp.async.wait_group 2;\n" ::: "memory");
        } else if (kt + 1 < KT_STEPS) {
            asm volatile("cp.async.wait_group 1;\n" ::: "memory");
        } else {
            asm volatile("cp.async.wait_group 0;\n" ::: "memory");
        }
        __syncthreads();

        const char* Ab = smem + (kt % NSTAGE) * STG_BOTH;
        const char* Bb = Ab + A_STG;

#pragma unroll
        for (int ks = 0; ks < 4; ++ks) {     // 4 x k16 per chunk
            uint32_t af[2][4], bf[4][4];
#pragma unroll
            for (int i = 0; i < 2; ++i)
                ldsm4(af[i], Ab + (wm * 32 + i * 16 + lrow) * SROW + ks * 32 + lcol);
#pragma unroll
            for (int j4 = 0; j4 < 4; ++j4)
                ldsm4(bf[j4], Bb + (wn * 64 + j4 * 16 + lrow) * SROW + ks * 32 + lcol);
#pragma unroll
            for (int i = 0; i < 2; ++i)
#pragma unroll
                for (int j = 0; j < 8; ++j) {
                    int j2 = j >> 1, hi = j & 1;
                    mma_f16(acc[i][j], af[i],
                            hi ? bf[j2][1] : bf[j2][0],
                            hi ? bf[j2][3] : bf[j2][2]);
                }
        }
        __syncthreads();
    }

    // ---- epilogue: two 128-col halves via smem transpose (stride 129) ------
    float* sbuf = (float*)smem;              // 128 x 129 floats = 66048 B
    float osc = g_sx * g_sw;
    int b_img = (int)(m0 >> 12);
    int p0 = (int)(m0 & 4095);
    int grp = lane >> 2, tig = lane & 3;

#pragma unroll
    for (int nh = 0; nh < 2; ++nh) {
        __syncthreads();
        if ((wn >> 1) == nh) {
#pragma unroll
            for (int i = 0; i < 2; ++i)
#pragma unroll
                for (int j = 0; j < 8; ++j)
#pragma unroll
                    for (int r = 0; r < 4; ++r) {
                        int m  = wm * 32 + i * 16 + grp + (r >> 1) * 8;
                        int nl = (wn & 1) * 64 + j * 8 + tig * 2 + (r & 1);
                        sbuf[m * 129 + nl] = acc[i][j][r];
                    }
        }
        __syncthreads();

        int pos = tid & 127, cg = tid >> 7;  // 4 channel groups of 32
#pragma unroll
        for (int t = 0; t < 32; ++t) {
            int o  = nh * 128 + cg * 32 + t;
            float v = sbuf[pos * 129 + (o - nh * 128)] * osc + __ldg(&bias[o]);
            out[(((size_t)b_img * C_OUTC + o) << 12) + p0 + pos] = v;
        }
    }
}

// ---------------- launch -----------------------------------------------------
extern "C" void kernel_launch(void* const* d_in, const int* in_sizes, int n_in,
                              void* d_out, int out_size) {
    const float* x    = (const float*)d_in[0];
    const float* wt   = (const float*)d_in[1];
    const float* bias = (const float*)d_in[2];
    float* out = (float*)d_out;

    cudaFuncSetAttribute(k_aq, cudaFuncAttributeMaxDynamicSharedMemorySize,
                         AQ_SMEM);
    cudaFuncSetAttribute(k_gemm_h, cudaFuncAttributeMaxDynamicSharedMemorySize,
                         GEMM_SMEM);

    k_wscale<<<(KKC + 255) / 256, 256>>>(wt);
    k_ascale<<<dim3(C_INC, BSZ), 256>>>(x);
    k_scale<<<1, 256>>>();
    k_wq<<<(C_OUTC * KKC) / 256, 256>>>(wt);
    k_aq<<<dim3(BSZ * HDIM, 2), 256, AQ_SMEM>>>(x);
    k_gemm_h<<<M_TOT / BM, 512, GEMM_SMEM>>>(bias, out);
}

// round 10
// speedup vs baseline: 1.0697x; 1.0697x over previous
#include <cuda_runtime.h>
#include <cuda_fp16.h>
#include <cstdint>
#include <cstddef>

// ---------------- problem constants ----------------
#define C_INC   128
#define C_OUTC  256
#define HDIM    64
#define WDIM    64
#define BSZ     16
#define KKC     1152          // C_IN * 9
#define M_TOT   65536
#define L_IMG   4096

// ---------------- k_aq staging ----------------
#define STRH    1156
#define AQ_SMEM (576*4 + 8*3*66*4 + 64*STRH)   // 82624

// ---------------- GEMM tiling ----------------
#define BM   128
#define BN   128
#define KT_STEPS 18           // chunks of 64 halves (128 B)
#define SROW 144              // smem row stride bytes
#define A_STG (BM * SROW)     // 18432
#define B_STG (BN * SROW)     // 18432
#define STG_BOTH (A_STG + B_STG)   // 36864
#define NSTAGE 3
#define GEMM_SMEM (NSTAGE * STG_BOTH)   // 110592 (epilogue sbuf 66048 fits)

// ---------------- device scratch ----------------
__device__ float g_wscale[KKC];
__device__ float g_ascale[KKC];
__device__ float g_scale[KKC];
__device__ float g_qfx[KKC];
__device__ float g_sx;
__device__ float g_sw;
__device__ __align__(16) __half g_wq_h[C_OUTC * KKC];
__device__ __align__(16) __half g_aq_h[(size_t)M_TOT * KKC];   // 151 MB

// ---------------- K1: weight per-column max (+ reset ascale) ----------------
__global__ void k_wscale(const float* __restrict__ w) {
    int j = blockIdx.x * blockDim.x + threadIdx.x;
    if (j >= KKC) return;
    g_ascale[j] = 0.f;
    float m = 0.f;
    for (int o = 0; o < C_OUTC; ++o)
        m = fmaxf(m, fabsf(w[o * KKC + j]));
    g_wscale[j] = m;
}

// ---------------- K2: activation per-(c,kh,kw) max -------------------------
__global__ void k_ascale(const float* __restrict__ x) {
    int c = blockIdx.x, b = blockIdx.y;
    float m[9];
#pragma unroll
    for (int v = 0; v < 9; ++v) m[v] = 0.f;

    const float* xb = x + (((size_t)b * C_INC + c) << 12);
    for (int p = threadIdx.x; p < L_IMG; p += 256) {
        int h = p >> 6, w = p & 63;
        float a = fabsf(xb[p]);
        bool h0 = (h < HDIM - 1);
        bool h2 = (h > 0);
        bool w0 = (w < WDIM - 1);
        bool w2 = (w > 0);
        if (h0 && w0) m[0] = fmaxf(m[0], a);
        if (h0)       m[1] = fmaxf(m[1], a);
        if (h0 && w2) m[2] = fmaxf(m[2], a);
        if (w0)       m[3] = fmaxf(m[3], a);
        m[4] = fmaxf(m[4], a);
        if (w2)       m[5] = fmaxf(m[5], a);
        if (h2 && w0) m[6] = fmaxf(m[6], a);
        if (h2)       m[7] = fmaxf(m[7], a);
        if (h2 && w2) m[8] = fmaxf(m[8], a);
    }

    __shared__ float sm[256];
    for (int v = 0; v < 9; ++v) {
        sm[threadIdx.x] = m[v];
        __syncthreads();
        for (int s = 128; s > 0; s >>= 1) {
            if (threadIdx.x < s)
                sm[threadIdx.x] = fmaxf(sm[threadIdx.x], sm[threadIdx.x + s]);
            __syncthreads();
        }
        if (threadIdx.x == 0)
            atomicMax((int*)&g_ascale[c * 9 + v], __float_as_int(sm[0]));
        __syncthreads();
    }
}

// ---------------- K3: smooth scales + per-tensor quant scales ---------------
__global__ void k_scale() {
    __shared__ float red[256];
    __shared__ float s_sx_sh;
    int tid = threadIdx.x;

    float mx = 0.f, mw = 0.f;
    for (int j = tid; j < KKC; j += 256) {
        float a = g_ascale[j];
        float w = g_wscale[j];
        float s = __fdiv_rn(__fsqrt_rn(a), __fsqrt_rn(w));
        if (s == 0.f) s = 1.f;
        g_scale[j] = s;
        mx = fmaxf(mx, __fdiv_rn(a, s));
        mw = fmaxf(mw, w * s);
    }

    red[tid] = mx; __syncthreads();
    for (int s = 128; s > 0; s >>= 1) {
        if (tid < s) red[tid] = fmaxf(red[tid], red[tid + s]);
        __syncthreads();
    }
    if (tid == 0) {
        float sx = __fdiv_rn(red[0], 127.f);
        if (sx == 0.f) sx = 1.f;
        g_sx = sx; s_sx_sh = sx;
    }
    __syncthreads();

    red[tid] = mw; __syncthreads();
    for (int s = 128; s > 0; s >>= 1) {
        if (tid < s) red[tid] = fmaxf(red[tid], red[tid + s]);
        __syncthreads();
    }
    if (tid == 0) {
        float sw = __fdiv_rn(red[0], 127.f);
        if (sw == 0.f) sw = 1.f;
        g_sw = sw;
    }
    __syncthreads();

    float sx = s_sx_sh;
    for (int j = tid; j < KKC; j += 256)
        g_qfx[j] = __fdiv_rn(1.f, g_scale[j] * sx);
}

// ---------------- K4: quantize weights -> fp16 ------------------------------
__global__ void k_wq(const float* __restrict__ w) {
    int i = blockIdx.x * blockDim.x + threadIdx.x;
    if (i >= C_OUTC * KKC) return;
    int j = i % KKC;
    float t = w[i] * g_scale[j];
    float q = rintf(__fdiv_rn(t, g_sw));
    q = fminf(fmaxf(q, -127.f), 127.f);
    g_wq_h[i] = __float2half_rn(q);
}

// ---------------- K5: fused im2col + quantization -> fp16 -------------------
__global__ void __launch_bounds__(256) k_aq(const float* __restrict__ x) {
    extern __shared__ char dsm[];
    float*  qfx_s = (float*)dsm;
    float*  xs    = qfx_s + 576;
    __half* aqs   = (__half*)(xs + 8 * 3 * 66);

    int tid = threadIdx.x;
    int bh  = blockIdx.x;
    int ch2 = blockIdx.y;
    int b   = bh >> 6, h = bh & 63;
    int g   = tid >> 5, lane = tid & 31;

    for (int j = tid; j < 576; j += 256) qfx_s[j] = g_qfx[ch2 * 576 + j];

    float* xg = xs + g * (3 * 66);

    for (int c0 = 0; c0 < 64; c0 += 8) {
        int cl = c0 + g;
        int c  = ch2 * 64 + cl;
        __syncthreads();
        const float* xb = x + (((size_t)b * C_INC + c) << 12);
#pragma unroll
        for (int r = 0; r < 3; ++r) {
            int hh = h + r - 1;
            float v0 = 0.f, v1 = 0.f;
            if ((unsigned)hh < (unsigned)HDIM) {
                v0 = xb[(hh << 6) + lane];
                v1 = xb[(hh << 6) + lane + 32];
            }
            xg[r * 66 + 1 + lane]  = v0;
            xg[r * 66 + 33 + lane] = v1;
            if (lane == 0) { xg[r * 66] = 0.f; xg[r * 66 + 65] = 0.f; }
        }
        __syncthreads();
#pragma unroll
        for (int half = 0; half < 2; ++half) {
            int w = lane + half * 32;
            __half* ar = (__half*)((char*)aqs + w * STRH);
#pragma unroll
            for (int e = 0; e < 9; ++e) {
                const int kh = e / 3, kw = e % 3;
                float v = xg[kh * 66 + w + kw];
                float q = rintf(v * qfx_s[cl * 9 + e]);
                q = fminf(fmaxf(q, -127.f), 127.f);
                ar[cl * 9 + e] = __float2half_rn(q);
            }
        }
    }
    __syncthreads();

    int* dst = (int*)g_aq_h;
    for (int idx = tid; idx < 64 * 288; idx += 256) {
        int row = idx / 288;
        int col = idx - row * 288;
        dst[((size_t)(bh * 64 + row)) * 576 + ch2 * 288 + col] =
            *(const int*)((char*)aqs + row * STRH + col * 4);
    }
}

// ---------------- K6: fp16 HMMA GEMM (n-fastest grid, 3-stage, occ 2) -------
__device__ __forceinline__ void cp16(void* smem_dst, const void* gmem_src) {
    unsigned s = (unsigned)__cvta_generic_to_shared(smem_dst);
    asm volatile("cp.async.cg.shared.global [%0], [%1], 16;\n"
                 :: "r"(s), "l"(gmem_src));
}

__device__ __forceinline__ void ldsm4(uint32_t* r, const void* p) {
    unsigned a = (unsigned)__cvta_generic_to_shared(p);
    asm volatile("ldmatrix.sync.aligned.m8n8.x4.shared.b16 {%0,%1,%2,%3}, [%4];"
                 : "=r"(r[0]), "=r"(r[1]), "=r"(r[2]), "=r"(r[3]) : "r"(a));
}

__device__ __forceinline__ void mma_f16(float* c, const uint32_t* a,
                                        uint32_t b0, uint32_t b1) {
    asm volatile(
        "mma.sync.aligned.m16n8k16.row.col.f32.f16.f16.f32 "
        "{%0,%1,%2,%3}, {%4,%5,%6,%7}, {%8,%9}, {%0,%1,%2,%3};\n"
        : "+f"(c[0]), "+f"(c[1]), "+f"(c[2]), "+f"(c[3])
        : "r"(a[0]), "r"(a[1]), "r"(a[2]), "r"(a[3]), "r"(b0), "r"(b1));
}

__global__ void __launch_bounds__(256, 2) k_gemm_h(const float* __restrict__ bias,
                                                   float* __restrict__ out) {
    extern __shared__ __align__(16) char smem[];

    int tid = threadIdx.x;
    int warpId = tid >> 5, lane = tid & 31;
    int wm = warpId & 1, wn = warpId >> 1;   // 2(m) x 4(n); warp tile 64x32
    // n fastest: both n-tiles of an m-tile run concurrently -> A shared in L2
    size_t m0 = (size_t)blockIdx.y * BM;
    int    n0 = blockIdx.x * BN;

    float acc[4][4][4];
#pragma unroll
    for (int i = 0; i < 4; ++i)
#pragma unroll
        for (int j = 0; j < 4; ++j)
#pragma unroll
            for (int r = 0; r < 4; ++r) acc[i][j][r] = 0.f;

    const char* Ag = (const char*)g_aq_h;    // row stride 2304 B
    const char* Bg = (const char*)g_wq_h;

    auto load_stage = [&](int kt, int s) {
        char* As = smem + s * STG_BOTH;
        char* Bs = As + A_STG;
#pragma unroll
        for (int it = 0; it < 4; ++it) {
            int f = tid + it * 256;          // 1024 granules per operand
            int row = f >> 3, c16 = f & 7;
            cp16(As + row * SROW + c16 * 16,
                 Ag + (m0 + row) * 2304 + kt * 128 + c16 * 16);
            cp16(Bs + row * SROW + c16 * 16,
                 Bg + (size_t)(n0 + row) * 2304 + kt * 128 + c16 * 16);
        }
        asm volatile("cp.async.commit_group;\n" ::: "memory");
    };

    load_stage(0, 0);
    load_stage(1, 1);

    int lrow = lane & 15;
    int lcol = (lane >> 4) * 16;

    for (int kt = 0; kt < KT_STEPS; ++kt) {
        if (kt + 2 < KT_STEPS) {
            load_stage(kt + 2, (kt + 2) % NSTAGE);
            asm volatile("cp.async.wait_group 2;\n" ::: "memory");
        } else if (kt + 1 < KT_STEPS) {
            asm volatile("cp.async.wait_group 1;\n" ::: "memory");
        } else {
            asm volatile("cp.async.wait_group 0;\n" ::: "memory");
        }
        __syncthreads();

        const char* Ab = smem + (kt % NSTAGE) * STG_BOTH;
        const char* Bb = Ab + A_STG;

#pragma unroll
        for (int ks = 0; ks < 4; ++ks) {     // 4 x k16 per 64-half chunk
            uint32_t af[4][4], bf[2][4];
#pragma unroll
            for (int i = 0; i < 4; ++i)
                ldsm4(af[i], Ab + (wm * 64 + i * 16 + lrow) * SROW + ks * 32 + lcol);
#pragma unroll
            for (int j2 = 0; j2 < 2; ++j2)
                ldsm4(bf[j2], Bb + (wn * 32 + j2 * 16 + lrow) * SROW + ks * 32 + lcol);
#pragma unroll
            for (int i = 0; i < 4; ++i)
#pragma unroll
                for (int j = 0; j < 4; ++j) {
                    int j2 = j >> 1, hi = j & 1;
                    mma_f16(acc[i][j], af[i],
                            hi ? bf[j2][1] : bf[j2][0],
                            hi ? bf[j2][3] : bf[j2][2]);
                }
        }
        __syncthreads();
    }

    // ---- epilogue: smem transpose (stride 129) -> float4 NCHW stores -------
    float* sbuf = (float*)smem;              // 128 x 129 floats = 66048 B
    int grp = lane >> 2, tig = lane & 3;
    __syncthreads();
#pragma unroll
    for (int i = 0; i < 4; ++i)
#pragma unroll
        for (int j = 0; j < 4; ++j)
#pragma unroll
            for (int r = 0; r < 4; ++r) {
                int m = wm * 64 + i * 16 + grp + (r >> 1) * 8;
                int n = wn * 32 + j * 8 + tig * 2 + (r & 1);
                sbuf[m * 129 + n] = acc[i][j][r];
            }
    __syncthreads();

    float osc = g_sx * g_sw;
    int b_img = (int)(m0 >> 12);
    int p0 = (int)(m0 & 4095);
    int og = tid >> 5;                       // 8 channel groups
    int mv = lane * 4;                       // 4 consecutive m per thread
#pragma unroll
    for (int rep = 0; rep < 16; ++rep) {
        int nl = og + rep * 8;               // local channel 0..127
        int o  = n0 + nl;
        float bz = __ldg(&bias[o]);
        float4 v;
        v.x = sbuf[(mv + 0) * 129 + nl] * osc + bz;
        v.y = sbuf[(mv + 1) * 129 + nl] * osc + bz;
        v.z = sbuf[(mv + 2) * 129 + nl] * osc + bz;
        v.w = sbuf[(mv + 3) * 129 + nl] * osc + bz;
        *(float4*)(out + (((size_t)b_img * C_OUTC + o) << 12) + p0 + mv) = v;
    }
}

// ---------------- launch -----------------------------------------------------
extern "C" void kernel_launch(void* const* d_in, const int* in_sizes, int n_in,
                              void* d_out, int out_size) {
    const float* x    = (const float*)d_in[0];
    const float* wt   = (const float*)d_in[1];
    const float* bias = (const float*)d_in[2];
    float* out = (float*)d_out;

    cudaFuncSetAttribute(k_aq, cudaFuncAttributeMaxDynamicSharedMemorySize,
                         AQ_SMEM);
    cudaFuncSetAttribute(k_gemm_h, cudaFuncAttributeMaxDynamicSharedMemorySize,
                         GEMM_SMEM);

    k_wscale<<<(KKC + 255) / 256, 256>>>(wt);
    k_ascale<<<dim3(C_INC, BSZ), 256>>>(x);
    k_scale<<<1, 256>>>();
    k_wq<<<(C_OUTC * KKC) / 256, 256>>>(wt);
    k_aq<<<dim3(BSZ * HDIM, 2), 256, AQ_SMEM>>>(x);
    k_gemm_h<<<dim3(C_OUTC / BN, M_TOT / BM), 256, GEMM_SMEM>>>(bias, out);
}

// round 11
// speedup vs baseline: 1.2939x; 1.2096x over previous
#include <cuda_runtime.h>
#include <cuda_fp16.h>
#include <cstdint>
#include <cstddef>

// ---------------- problem constants ----------------
#define C_INC   128
#define C_OUTC  256
#define HDIM    64
#define WDIM    64
#define BSZ     16
#define KKC     1152          // C_IN * 9
#define M_TOT   65536
#define L_IMG   4096

// ---------------- fused GEMM tiling ----------------
#define BM   128              // 2 image rows
#define BN   128
#define NCHK 16               // chunks of 8 channels (72 k-values, padded to 80)
#define AROW 176              // smem row stride bytes (160 data+pad, ldsm-conflict-free)
#define B_STG (128 * AROW)    // 22528
#define X_STG (8 * 4 * 256)   // 8192 (8 ch x 4 rows x 64 floats)
#define A_OFF (3 * B_STG)             // 67584
#define X_OFF (A_OFF + B_STG)         // 90112
#define Q_OFF (X_OFF + 3 * X_STG)     // 114688
#define GEMM_SMEM (Q_OFF + 3 * 288)   // 115552  (<= 116736 for occupancy 2)

// ---------------- device scratch ----------------
__device__ float g_wscale[KKC];
__device__ float g_ascale[KKC];
__device__ float g_scale[KKC];
__device__ float g_qfx[KKC];
__device__ float g_sx;
__device__ float g_sw;
__device__ __align__(16) __half g_wq_h[C_OUTC * KKC];

// ---------------- K1: weight per-column max (+ reset ascale) ----------------
__global__ void k_wscale(const float* __restrict__ w) {
    int j = blockIdx.x * blockDim.x + threadIdx.x;
    if (j >= KKC) return;
    g_ascale[j] = 0.f;
    float m = 0.f;
    for (int o = 0; o < C_OUTC; ++o)
        m = fmaxf(m, fabsf(w[o * KKC + j]));
    g_wscale[j] = m;
}

// ---------------- K2: activation per-(c,kh,kw) max -------------------------
__global__ void k_ascale(const float* __restrict__ x) {
    int c = blockIdx.x, b = blockIdx.y;
    float m[9];
#pragma unroll
    for (int v = 0; v < 9; ++v) m[v] = 0.f;

    const float* xb = x + (((size_t)b * C_INC + c) << 12);
    for (int p = threadIdx.x; p < L_IMG; p += 256) {
        int h = p >> 6, w = p & 63;
        float a = fabsf(xb[p]);
        bool h0 = (h < HDIM - 1);
        bool h2 = (h > 0);
        bool w0 = (w < WDIM - 1);
        bool w2 = (w > 0);
        if (h0 && w0) m[0] = fmaxf(m[0], a);
        if (h0)       m[1] = fmaxf(m[1], a);
        if (h0 && w2) m[2] = fmaxf(m[2], a);
        if (w0)       m[3] = fmaxf(m[3], a);
        m[4] = fmaxf(m[4], a);
        if (w2)       m[5] = fmaxf(m[5], a);
        if (h2 && w0) m[6] = fmaxf(m[6], a);
        if (h2)       m[7] = fmaxf(m[7], a);
        if (h2 && w2) m[8] = fmaxf(m[8], a);
    }

    __shared__ float sm[256];
    for (int v = 0; v < 9; ++v) {
        sm[threadIdx.x] = m[v];
        __syncthreads();
        for (int s = 128; s > 0; s >>= 1) {
            if (threadIdx.x < s)
                sm[threadIdx.x] = fmaxf(sm[threadIdx.x], sm[threadIdx.x + s]);
            __syncthreads();
        }
        if (threadIdx.x == 0)
            atomicMax((int*)&g_ascale[c * 9 + v], __float_as_int(sm[0]));
        __syncthreads();
    }
}

// ---------------- K3: smooth scales + per-tensor quant scales ---------------
__global__ void k_scale() {
    __shared__ float red[256];
    __shared__ float s_sx_sh;
    int tid = threadIdx.x;

    float mx = 0.f, mw = 0.f;
    for (int j = tid; j < KKC; j += 256) {
        float a = g_ascale[j];
        float w = g_wscale[j];
        float s = __fdiv_rn(__fsqrt_rn(a), __fsqrt_rn(w));
        if (s == 0.f) s = 1.f;
        g_scale[j] = s;
        mx = fmaxf(mx, __fdiv_rn(a, s));
        mw = fmaxf(mw, w * s);
    }

    red[tid] = mx; __syncthreads();
    for (int s = 128; s > 0; s >>= 1) {
        if (tid < s) red[tid] = fmaxf(red[tid], red[tid + s]);
        __syncthreads();
    }
    if (tid == 0) {
        float sx = __fdiv_rn(red[0], 127.f);
        if (sx == 0.f) sx = 1.f;
        g_sx = sx; s_sx_sh = sx;
    }
    __syncthreads();

    red[tid] = mw; __syncthreads();
    for (int s = 128; s > 0; s >>= 1) {
        if (tid < s) red[tid] = fmaxf(red[tid], red[tid + s]);
        __syncthreads();
    }
    if (tid == 0) {
        float sw = __fdiv_rn(red[0], 127.f);
        if (sw == 0.f) sw = 1.f;
        g_sw = sw;
    }
    __syncthreads();

    float sx = s_sx_sh;
    for (int j = tid; j < KKC; j += 256)
        g_qfx[j] = __fdiv_rn(1.f, g_scale[j] * sx);
}

// ---------------- K4: quantize weights -> fp16 ------------------------------
__global__ void k_wq(const float* __restrict__ w) {
    int i = blockIdx.x * blockDim.x + threadIdx.x;
    if (i >= C_OUTC * KKC) return;
    int j = i % KKC;
    float t = w[i] * g_scale[j];
    float q = rintf(__fdiv_rn(t, g_sw));
    q = fminf(fmaxf(q, -127.f), 127.f);
    g_wq_h[i] = __float2half_rn(q);
}

// ---------------- helpers ----------------------------------------------------
__device__ __forceinline__ void cp16(void* smem_dst, const void* gmem_src) {
    unsigned s = (unsigned)__cvta_generic_to_shared(smem_dst);
    asm volatile("cp.async.cg.shared.global [%0], [%1], 16;\n"
                 :: "r"(s), "l"(gmem_src));
}
__device__ __forceinline__ void cp16z(void* smem_dst, const void* gmem_src, int sz) {
    unsigned s = (unsigned)__cvta_generic_to_shared(smem_dst);
    asm volatile("cp.async.cg.shared.global [%0], [%1], 16, %2;\n"
                 :: "r"(s), "l"(gmem_src), "r"(sz));
}
__device__ __forceinline__ void ldsm4(uint32_t* r, const void* p) {
    unsigned a = (unsigned)__cvta_generic_to_shared(p);
    asm volatile("ldmatrix.sync.aligned.m8n8.x4.shared.b16 {%0,%1,%2,%3}, [%4];"
                 : "=r"(r[0]), "=r"(r[1]), "=r"(r[2]), "=r"(r[3]) : "r"(a));
}
__device__ __forceinline__ void mma_f16(float* c, const uint32_t* a,
                                        uint32_t b0, uint32_t b1) {
    asm volatile(
        "mma.sync.aligned.m16n8k16.row.col.f32.f16.f16.f32 "
        "{%0,%1,%2,%3}, {%4,%5,%6,%7}, {%8,%9}, {%0,%1,%2,%3};\n"
        : "+f"(c[0]), "+f"(c[1]), "+f"(c[2]), "+f"(c[3])
        : "f"(c[0]) : );
}

// real mma wrapper (above stub replaced below to keep operand list correct)
__device__ __forceinline__ void mma_f16v(float* c, const uint32_t* a,
                                         uint32_t b0, uint32_t b1) {
    asm volatile(
        "mma.sync.aligned.m16n8k16.row.col.f32.f16.f16.f32 "
        "{%0,%1,%2,%3}, {%4,%5,%6,%7}, {%8,%9}, {%0,%1,%2,%3};\n"
        : "+f"(c[0]), "+f"(c[1]), "+f"(c[2]), "+f"(c[3])
        : "r"(a[0]), "r"(a[1]), "r"(a[2]), "r"(a[3]), "r"(b0), "r"(b1));
}

// ---------------- K5: FUSED im2col + quantize + fp16 HMMA GEMM --------------
__global__ void __launch_bounds__(256, 2) k_gemm_f(const float* __restrict__ x,
                                                   const float* __restrict__ bias,
                                                   float* __restrict__ out) {
    extern __shared__ __align__(16) char smem[];

    int tid = threadIdx.x;
    int warpId = tid >> 5, lane = tid & 31;
    int wm = warpId & 1, wn = warpId >> 1;     // 2(m) x 4(n); warp tile 64x32
    int n0 = blockIdx.x * BN;
    size_t m0 = (size_t)blockIdx.y * BM;
    int b  = (int)(m0 >> 12);
    int h0 = (int)((m0 & 4095) >> 6);          // first of 2 image rows

    // conversion thread mapping
    int p   = tid & 127;                       // position within tile
    int grpC = tid >> 7;                       // channel half (0/1)
    int hl  = p >> 6, w = p & 63;

    float acc[4][4][4];
#pragma unroll
    for (int i = 0; i < 4; ++i)
#pragma unroll
        for (int j = 0; j < 4; ++j)
#pragma unroll
            for (int r = 0; r < 4; ++r) acc[i][j][r] = 0.f;

    const char* Bg = (const char*)g_wq_h;      // row stride 2304 B
    const float* xb = x + ((size_t)b * C_INC << 12);

    // zero the k-pad columns [144,160) of A tile + all 3 B stages (written once)
    {
        float4 z = make_float4(0.f, 0.f, 0.f, 0.f);
        for (int f = tid; f < 512; f += 256) {
            int buf = f >> 7, row = f & 127;
            char* base = (buf < 3) ? (smem + buf * B_STG) : (smem + A_OFF);
            *(float4*)(base + row * AROW + 144) = z;
        }
    }

    auto load_chunk = [&](int kt, int st) {
        char* Bs = smem + st * B_STG;
        char* Xs = smem + X_OFF + st * X_STG;
        char* Qs = smem + Q_OFF + st * 288;
        // B: 128 rows x 144 B = 1152 granules
        for (int f = tid; f < 1152; f += 256) {
            int row = f / 9, g = f - row * 9;
            cp16(Bs + row * AROW + g * 16,
                 Bg + (size_t)(n0 + row) * 2304 + kt * 144 + g * 16);
        }
        // x strip: 8 ch x 4 rows x 256 B = 512 granules (zfill out-of-image rows)
        int c0 = kt * 8;
        for (int f = tid; f < 512; f += 256) {
            int ci = f >> 6, r = (f >> 4) & 3, g = f & 15;
            int hh = h0 - 1 + r;
            int ok = ((unsigned)hh < 64u);
            int hc = ok ? hh : 0;
            const char* src = (const char*)(xb + (((size_t)(c0 + ci)) << 12) + (hc << 6)) + g * 16;
            cp16z(Xs + (ci * 4 + r) * 256 + g * 16, src, ok ? 16 : 0);
        }
        // qfx slice: 72 floats = 18 granules
        if (tid < 18)
            cp16(Qs + tid * 16, (const char*)g_qfx + kt * 288 + tid * 16);
        asm volatile("cp.async.commit_group;\n" ::: "memory");
    };

    load_chunk(0, 0);
    load_chunk(1, 1);

    int lrow = lane & 15;
    int lcol = (lane >> 4) * 16;

    for (int kt = 0; kt < NCHK; ++kt) {
        if (kt + 1 < NCHK) {
            asm volatile("cp.async.wait_group 1;\n" ::: "memory");
        } else {
            asm volatile("cp.async.wait_group 0;\n" ::: "memory");
        }
        __syncthreads();   // chunk kt data ready; prior ldsm complete

        // ---- convert: x strip -> quantized fp16 A tile (128 x 72) ----
        {
            int st = kt % 3;
            const float* Xf = (const float*)(smem + X_OFF + st * X_STG);
            const float* Qf = (const float*)(smem + Q_OFF + st * 288);
            __half* Ar = (__half*)(smem + A_OFF + p * AROW);
#pragma unroll
            for (int cc = 0; cc < 4; ++cc) {
                int ci = grpC * 4 + cc;
#pragma unroll
                for (int kh = 0; kh < 3; ++kh) {
                    const float* xr = Xf + (ci * 4 + hl + kh) * 64;
                    float fa = (w > 0)  ? xr[w - 1] : 0.f;
                    float fb = xr[w];
                    float fc = (w < 63) ? xr[w + 1] : 0.f;
                    int e = ci * 9 + kh * 3;
                    float q0 = fminf(fmaxf(rintf(fa * Qf[e - ci * 9 + ci * 9]), -127.f), 127.f);
                    // (expression kept simple below)
                    q0 = fminf(fmaxf(rintf(fa * Qf[ci * 9 + kh * 3 + 0]), -127.f), 127.f);
                    float q1 = fminf(fmaxf(rintf(fb * Qf[ci * 9 + kh * 3 + 1]), -127.f), 127.f);
                    float q2 = fminf(fmaxf(rintf(fc * Qf[ci * 9 + kh * 3 + 2]), -127.f), 127.f);
                    Ar[e]     = __float2half_rn(q0);
                    Ar[e + 1] = __float2half_rn(q1);
                    Ar[e + 2] = __float2half_rn(q2);
                }
            }
        }
        __syncthreads();   // A tile ready; x stage free

        if (kt + 2 < NCHK) load_chunk(kt + 2, (kt + 2) % 3);

        // ---- MMA: 5 k16 steps (72 real + 8 zero-pad halves) ----
        const char* Ab = smem + A_OFF;
        const char* Bb = smem + (kt % 3) * B_STG;
#pragma unroll
        for (int ks = 0; ks < 5; ++ks) {
            uint32_t af[4][4], bf[2][4];
#pragma unroll
            for (int i = 0; i < 4; ++i)
                ldsm4(af[i], Ab + (wm * 64 + i * 16 + lrow) * AROW + ks * 32 + lcol);
#pragma unroll
            for (int j2 = 0; j2 < 2; ++j2)
                ldsm4(bf[j2], Bb + (wn * 32 + j2 * 16 + lrow) * AROW + ks * 32 + lcol);
#pragma unroll
            for (int i = 0; i < 4; ++i)
#pragma unroll
                for (int j = 0; j < 4; ++j) {
                    int j2 = j >> 1, hi = j & 1;
                    mma_f16v(acc[i][j], af[i],
                             hi ? bf[j2][1] : bf[j2][0],
                             hi ? bf[j2][3] : bf[j2][2]);
                }
        }
    }

    // ---- epilogue: smem transpose (stride 129) -> float4 NCHW stores -------
    float* sbuf = (float*)smem;              // 128 x 129 floats
    int grp = lane >> 2, tig = lane & 3;
    __syncthreads();
#pragma unroll
    for (int i = 0; i < 4; ++i)
#pragma unroll
        for (int j = 0; j < 4; ++j)
#pragma unroll
            for (int r = 0; r < 4; ++r) {
                int m = wm * 64 + i * 16 + grp + (r >> 1) * 8;
                int n = wn * 32 + j * 8 + tig * 2 + (r & 1);
                sbuf[m * 129 + n] = acc[i][j][r];
            }
    __syncthreads();

    float osc = g_sx * g_sw;
    int p0 = (int)(m0 & 4095);
    int og = tid >> 5;                       // 8 channel groups
    int mv = lane * 4;
#pragma unroll
    for (int rep = 0; rep < 16; ++rep) {
        int nl = og + rep * 8;
        int o  = n0 + nl;
        float bz = __ldg(&bias[o]);
        float4 v;
        v.x = sbuf[(mv + 0) * 129 + nl] * osc + bz;
        v.y = sbuf[(mv + 1) * 129 + nl] * osc + bz;
        v.z = sbuf[(mv + 2) * 129 + nl] * osc + bz;
        v.w = sbuf[(mv + 3) * 129 + nl] * osc + bz;
        *(float4*)(out + (((size_t)b * C_OUTC + o) << 12) + p0 + mv) = v;
    }
}

// ---------------- launch -----------------------------------------------------
extern "C" void kernel_launch(void* const* d_in, const int* in_sizes, int n_in,
                              void* d_out, int out_size) {
    const float* x    = (const float*)d_in[0];
    const float* wt   = (const float*)d_in[1];
    const float* bias = (const float*)d_in[2];
    float* out = (float*)d_out;

    cudaFuncSetAttribute(k_gemm_f, cudaFuncAttributeMaxDynamicSharedMemorySize,
                         GEMM_SMEM);

    k_wscale<<<(KKC + 255) / 256, 256>>>(wt);
    k_ascale<<<dim3(C_INC, BSZ), 256>>>(x);
    k_scale<<<1, 256>>>();
    k_wq<<<(C_OUTC * KKC) / 256, 256>>>(wt);
    k_gemm_f<<<dim3(C_OUTC / BN, M_TOT / BM), 256, GEMM_SMEM>>>(x, bias, out);
}